// round 1
// baseline (speedup 1.0000x reference)
#include <cuda_runtime.h>

// VectorQuantizerEMA: N=16384 tokens, K=8192 codes, D=64.
// Outputs (fp32, concatenated): discrete[N*K], quantized[N*D], new_count[K],
// new_weight[K*D], new_codebook[K*D].

#define NTOK   16384
#define KCODES 8192
#define DIM    64
#define TM     128
#define TN     128
#define NCHUNK (KCODES / TN)   // 64
#define PADM   132             // padded row stride (floats), keeps 16B alignment
#define PADN   132
#define DECAYF 0.99f
#define OMDF   0.01f
#define EPSV   1e-5f
#define BATCHF 32.0f

// ---------------- device scratch (no allocations allowed) ----------------
__device__ float g_cnorm[KCODES];
__device__ float g_cnt[KCODES];
__device__ float g_wsum[KCODES * DIM];

// ---------------- packed f32x2 helpers ----------------
__device__ __forceinline__ unsigned long long pk2(float a, float b) {
    unsigned long long r;
    asm("mov.b64 %0, {%1, %2};" : "=l"(r) : "f"(a), "f"(b));
    return r;
}
__device__ __forceinline__ void upk2(unsigned long long v, float& a, float& b) {
    asm("mov.b64 {%0, %1}, %2;" : "=f"(a), "=f"(b) : "l"(v));
}
__device__ __forceinline__ unsigned long long fma2(unsigned long long a,
                                                   unsigned long long b,
                                                   unsigned long long c) {
    unsigned long long r;
    asm("fma.rn.f32x2 %0, %1, %2, %3;" : "=l"(r) : "l"(a), "l"(b), "l"(c));
    return r;
}

// ---------------- kernel 0: zero accumulators + codebook row norms ----------------
__global__ void vq_prep(const float* __restrict__ cb) {
    int g = blockIdx.x * blockDim.x + threadIdx.x;
    if (g < KCODES * DIM) g_wsum[g] = 0.0f;
    if (g < KCODES) {
        g_cnt[g] = 0.0f;
        const float4* r = (const float4*)(cb + (size_t)g * DIM);
        float s = 0.0f;
#pragma unroll
        for (int j = 0; j < 16; j++) {
            float4 v = r[j];
            s += v.x * v.x + v.y * v.y + v.z * v.z + v.w * v.w;
        }
        g_cnorm[g] = s;
    }
}

// ---------------- kernel 1: fused distance GEMM + argmin + one-hot + quantized ----------------
// Block: 256 threads = 16 (tx: code groups) x 16 (ty: token groups).
// Per thread: 8 tokens x 8 codes, accumulators packed as 8 x 4 f32x2 (pairs along codes).
// Interleaves the 512MB zero-fill of `discrete` with the FMA mainloop so the DRAM
// stores overlap FMA-pipe-bound compute.
extern "C" __global__ void __launch_bounds__(256)
vq_argmin(const float* __restrict__ x, const float* __restrict__ cb,
          float* __restrict__ discrete, float* __restrict__ quantized) {
    extern __shared__ float smem[];
    float* xs = smem;                 // [DIM][PADM] : xs[d*PADM + t]
    float* cs = smem + DIM * PADM;    // [DIM][PADN] : cs[d*PADN + k]

    const int tid = threadIdx.x;
    const int tx = tid & 15;          // code group
    const int ty = tid >> 4;          // token group
    const int m0 = blockIdx.x * TM;

    // Load x tile transposed into smem: xs[d][t] = x[m0+t][d]
    for (int i = tid; i < TM * DIM; i += 256) {
        int t = i >> 6, d = i & 63;
        xs[d * PADM + t] = x[(size_t)(m0 + t) * DIM + d];
    }

    float minv[8];
    int   mink[8];
#pragma unroll
    for (int t = 0; t < 8; t++) { minv[t] = 3.4e38f; mink[t] = 0; }

    const float4 z4 = make_float4(0.f, 0.f, 0.f, 0.f);

    for (int ch = 0; ch < NCHUNK; ch++) {
        const int k0 = ch * TN;
        __syncthreads();
        // Load code chunk transposed: cs[d][k] = cb[k0+k][d]
        for (int i = tid; i < TN * DIM; i += 256) {
            int k = i >> 6, d = i & 63;
            cs[d * PADN + k] = cb[(size_t)(k0 + k) * DIM + d];
        }
        __syncthreads();

        unsigned long long acc[8][4];
#pragma unroll
        for (int t = 0; t < 8; t++)
#pragma unroll
            for (int p = 0; p < 4; p++) acc[t][p] = 0ULL;

#pragma unroll 4
        for (int d = 0; d < DIM; d++) {
            const float4 xa = *(const float4*)&xs[d * PADM + ty * 8];
            const float4 xb = *(const float4*)&xs[d * PADM + ty * 8 + 4];
            const ulonglong2 cA = *(const ulonglong2*)&cs[d * PADN + tx * 8];
            const ulonglong2 cB = *(const ulonglong2*)&cs[d * PADN + tx * 8 + 4];
            float xv[8] = {xa.x, xa.y, xa.z, xa.w, xb.x, xb.y, xb.z, xb.w};
#pragma unroll
            for (int t = 0; t < 8; t++) {
                unsigned long long xd = pk2(xv[t], xv[t]);
                acc[t][0] = fma2(xd, cA.x, acc[t][0]);
                acc[t][1] = fma2(xd, cA.y, acc[t][1]);
                acc[t][2] = fma2(xd, cB.x, acc[t][2]);
                acc[t][3] = fma2(xd, cB.y, acc[t][3]);
            }
        }

        // Epilogue: dist = ||c||^2 - 2 x.c  (token-constant ||x||^2 dropped; argmin invariant)
        const float4 c0 = *(const float4*)&g_cnorm[k0 + tx * 8];
        const float4 c1 = *(const float4*)&g_cnorm[k0 + tx * 8 + 4];
        const float cn[8] = {c0.x, c0.y, c0.z, c0.w, c1.x, c1.y, c1.z, c1.w};
#pragma unroll
        for (int t = 0; t < 8; t++) {
#pragma unroll
            for (int p = 0; p < 4; p++) {
                float a0, a1;
                upk2(acc[t][p], a0, a1);
                float d0 = cn[2 * p]     - 2.0f * a0;
                float d1 = cn[2 * p + 1] - 2.0f * a1;
                int kk = k0 + tx * 8 + 2 * p;
                if (d0 < minv[t]) { minv[t] = d0; mink[t] = kk; }
                if (d1 < minv[t]) { minv[t] = d1; mink[t] = kk + 1; }
            }
        }

        // Interleaved zero-fill of the discrete tile [TM x TN] at (m0, k0):
        // 16384 floats / 256 threads = 16 float4 stores per thread per chunk.
#pragma unroll
        for (int it = 0; it < 16; it++) {
            int i = tid + it * 256;          // 0..4095
            int t = i >> 5;                  // 32 float4 per 128-col row
            int c4 = i & 31;
            *(float4*)(discrete + (size_t)(m0 + t) * KCODES + k0 + c4 * 4) = z4;
        }
    }

    // Final cross-thread argmin reduction (per token, over the 16 tx groups).
    __syncthreads();
    float* rv  = cs;                        // TM*16 floats
    int*   rk  = (int*)(cs + TM * 16);      // TM*16 ints
    int*   sidx = (int*)(cs + TM * 32);     // TM ints
#pragma unroll
    for (int t = 0; t < 8; t++) {
        rv[(ty * 8 + t) * 16 + tx] = minv[t];
        rk[(ty * 8 + t) * 16 + tx] = mink[t];
    }
    __syncthreads();
    if (tid < TM) {
        float bv = rv[tid * 16];
        int   bk = rk[tid * 16];
#pragma unroll
        for (int j = 1; j < 16; j++) {
            float v = rv[tid * 16 + j];
            int   k = rk[tid * 16 + j];
            if (v < bv || (v == bv && k < bk)) { bv = v; bk = k; }
        }
        sidx[tid] = bk;
        discrete[(size_t)(m0 + tid) * KCODES + bk] = 1.0f;
        atomicAdd(&g_cnt[bk], 1.0f);
    }
    __syncthreads();

    // quantized[m0+t][:] = codebook[idx]; EMA weight numerator scatter-add.
    for (int it = 0; it < (TM * DIM) / 256; it++) {   // 32 iters
        int i = tid + it * 256;
        int t = i >> 6, d = i & 63;
        int k = sidx[t];
        quantized[(size_t)(m0 + t) * DIM + d] = cb[(size_t)k * DIM + d];
        atomicAdd(&g_wsum[k * DIM + d], xs[d * PADM + t]);
    }
}

// ---------------- kernel 2: EMA finalize ----------------
__global__ void vq_finalize(const float* __restrict__ ema_count,
                            const float* __restrict__ ema_weight,
                            float* __restrict__ ocount,
                            float* __restrict__ oweight,
                            float* __restrict__ ocb) {
    int i = blockIdx.x * blockDim.x + threadIdx.x;
    if (i >= KCODES * DIM) return;
    int k = i >> 6, d = i & 63;
    float cnt  = ema_count[k] * DECAYF + g_cnt[k] * OMDF;
    float norm = (cnt + EPSV) / (BATCHF + (float)KCODES * EPSV) * BATCHF;
    if (d == 0) ocount[k] = norm;
    float w = ema_weight[i] * DECAYF + g_wsum[i] * OMDF;
    oweight[i] = w;
    ocb[i]     = w / norm;
}

// ---------------- launch ----------------
extern "C" void kernel_launch(void* const* d_in, const int* in_sizes, int n_in,
                              void* d_out, int out_size) {
    const float* x  = (const float*)d_in[0];
    const float* cb = (const float*)d_in[1];
    const float* ec = (const float*)d_in[2];
    const float* ew = (const float*)d_in[3];

    float* out       = (float*)d_out;
    float* discrete  = out;                                  // N*K
    float* quantized = discrete + (size_t)NTOK * KCODES;     // N*D
    float* ocount    = quantized + (size_t)NTOK * DIM;       // K
    float* oweight   = ocount + KCODES;                      // K*D
    float* ocb       = oweight + (size_t)KCODES * DIM;       // K*D

    vq_prep<<<(KCODES * DIM + 255) / 256, 256>>>(cb);

    const int smem_bytes = (DIM * PADM + DIM * PADN) * (int)sizeof(float);  // 67584
    cudaFuncSetAttribute((const void*)vq_argmin,
                         cudaFuncAttributeMaxDynamicSharedMemorySize, smem_bytes);
    vq_argmin<<<NTOK / TM, 256, smem_bytes>>>(x, cb, discrete, quantized);

    vq_finalize<<<(KCODES * DIM + 255) / 256, 256>>>(ec, ew, ocount, oweight, ocb);
}

// round 2
// speedup vs baseline: 1.0363x; 1.0363x over previous
#include <cuda_runtime.h>

// VectorQuantizerEMA: N=16384 tokens, K=8192 codes, D=64.
// Outputs (fp32, concatenated): discrete[N*K], quantized[N*D], new_count[K],
// new_weight[K*D], new_codebook[K*D].

#define NTOK   16384
#define KCODES 8192
#define DIM    64
#define TM     128
#define TN     128
#define NCHUNK (KCODES / TN)   // 64
#define PADM   132             // padded row stride (floats), keeps 16B alignment
#define PADN   132
#define DECAYF 0.99f
#define OMDF   0.01f
#define EPSV   1e-5f
#define BATCHF 32.0f

// ---------------- device scratch (no allocations allowed) ----------------
__device__ float g_cnorm[KCODES];
__device__ float g_cnt[KCODES];
__device__ float g_wsum[KCODES * DIM];

// ---------------- packed f32x2 helpers ----------------
__device__ __forceinline__ unsigned long long pk2(float a, float b) {
    unsigned long long r;
    asm("mov.b64 %0, {%1, %2};" : "=l"(r) : "f"(a), "f"(b));
    return r;
}
__device__ __forceinline__ void upk2(unsigned long long v, float& a, float& b) {
    asm("mov.b64 {%0, %1}, %2;" : "=f"(a), "=f"(b) : "l"(v));
}
__device__ __forceinline__ unsigned long long fma2(unsigned long long a,
                                                   unsigned long long b,
                                                   unsigned long long c) {
    unsigned long long r;
    asm("fma.rn.f32x2 %0, %1, %2, %3;" : "=l"(r) : "l"(a), "l"(b), "l"(c));
    return r;
}

// ---------------- kernel 0: zero accumulators + codebook row norms ----------------
__global__ void vq_prep(const float* __restrict__ cb) {
    int g = blockIdx.x * blockDim.x + threadIdx.x;
    if (g < KCODES * DIM) g_wsum[g] = 0.0f;
    if (g < KCODES) {
        g_cnt[g] = 0.0f;
        const float4* r = (const float4*)(cb + (size_t)g * DIM);
        float s = 0.0f;
#pragma unroll
        for (int j = 0; j < 16; j++) {
            float4 v = r[j];
            s += v.x * v.x + v.y * v.y + v.z * v.z + v.w * v.w;
        }
        g_cnorm[g] = s;
    }
}

// ---------------- kernel 1: fused distance GEMM + argmin + one-hot + quantized ----------------
// Block: 256 threads = 16 (tx: code groups) x 16 (ty: token groups).
// Per thread: 8 tokens x 8 codes, accumulators packed as 8 x 4 f32x2 (pairs along codes).
// Interleaves the 512MB zero-fill of `discrete` with the FMA mainloop so the DRAM
// stores overlap FMA-pipe-bound compute.
extern "C" __global__ void __launch_bounds__(256)
vq_argmin(const float* __restrict__ x, const float* __restrict__ cb,
          float* __restrict__ discrete, float* __restrict__ quantized) {
    extern __shared__ float smem[];
    float* xs = smem;                 // [DIM][PADM] : xs[d*PADM + t]
    float* cs = smem + DIM * PADM;    // [DIM][PADN] : cs[d*PADN + k]

    const int tid = threadIdx.x;
    const int tx = tid & 15;          // code group
    const int ty = tid >> 4;          // token group
    const int m0 = blockIdx.x * TM;

    // Load x tile transposed into smem: xs[d][t] = x[m0+t][d]
    for (int i = tid; i < TM * DIM; i += 256) {
        int t = i >> 6, d = i & 63;
        xs[d * PADM + t] = x[(size_t)(m0 + t) * DIM + d];
    }

    float minv[8];
    int   mink[8];
#pragma unroll
    for (int t = 0; t < 8; t++) { minv[t] = 3.4e38f; mink[t] = 0; }

    const float4 z4 = make_float4(0.f, 0.f, 0.f, 0.f);

    for (int ch = 0; ch < NCHUNK; ch++) {
        const int k0 = ch * TN;
        __syncthreads();
        // Load code chunk transposed: cs[d][k] = cb[k0+k][d]
        for (int i = tid; i < TN * DIM; i += 256) {
            int k = i >> 6, d = i & 63;
            cs[d * PADN + k] = cb[(size_t)(k0 + k) * DIM + d];
        }
        __syncthreads();

        unsigned long long acc[8][4];
#pragma unroll
        for (int t = 0; t < 8; t++)
#pragma unroll
            for (int p = 0; p < 4; p++) acc[t][p] = 0ULL;

#pragma unroll 4
        for (int d = 0; d < DIM; d++) {
            const float4 xa = *(const float4*)&xs[d * PADM + ty * 8];
            const float4 xb = *(const float4*)&xs[d * PADM + ty * 8 + 4];
            const ulonglong2 cA = *(const ulonglong2*)&cs[d * PADN + tx * 8];
            const ulonglong2 cB = *(const ulonglong2*)&cs[d * PADN + tx * 8 + 4];
            float xv[8] = {xa.x, xa.y, xa.z, xa.w, xb.x, xb.y, xb.z, xb.w};
#pragma unroll
            for (int t = 0; t < 8; t++) {
                unsigned long long xd = pk2(xv[t], xv[t]);
                acc[t][0] = fma2(xd, cA.x, acc[t][0]);
                acc[t][1] = fma2(xd, cA.y, acc[t][1]);
                acc[t][2] = fma2(xd, cB.x, acc[t][2]);
                acc[t][3] = fma2(xd, cB.y, acc[t][3]);
            }
        }

        // Epilogue: dist = ||c||^2 - 2 x.c  (token-constant ||x||^2 dropped; argmin invariant)
        const float4 c0 = *(const float4*)&g_cnorm[k0 + tx * 8];
        const float4 c1 = *(const float4*)&g_cnorm[k0 + tx * 8 + 4];
        const float cn[8] = {c0.x, c0.y, c0.z, c0.w, c1.x, c1.y, c1.z, c1.w};
#pragma unroll
        for (int t = 0; t < 8; t++) {
#pragma unroll
            for (int p = 0; p < 4; p++) {
                float a0, a1;
                upk2(acc[t][p], a0, a1);
                float d0 = cn[2 * p]     - 2.0f * a0;
                float d1 = cn[2 * p + 1] - 2.0f * a1;
                int kk = k0 + tx * 8 + 2 * p;
                if (d0 < minv[t]) { minv[t] = d0; mink[t] = kk; }
                if (d1 < minv[t]) { minv[t] = d1; mink[t] = kk + 1; }
            }
        }

        // Interleaved zero-fill of the discrete tile [TM x TN] at (m0, k0):
        // 16384 floats / 256 threads = 16 float4 stores per thread per chunk.
#pragma unroll
        for (int it = 0; it < 16; it++) {
            int i = tid + it * 256;          // 0..4095
            int t = i >> 5;                  // 32 float4 per 128-col row
            int c4 = i & 31;
            *(float4*)(discrete + (size_t)(m0 + t) * KCODES + k0 + c4 * 4) = z4;
        }
    }

    // Final cross-thread argmin reduction (per token, over the 16 tx groups).
    __syncthreads();
    float* rv  = cs;                        // TM*16 floats
    int*   rk  = (int*)(cs + TM * 16);      // TM*16 ints
    int*   sidx = (int*)(cs + TM * 32);     // TM ints
#pragma unroll
    for (int t = 0; t < 8; t++) {
        rv[(ty * 8 + t) * 16 + tx] = minv[t];
        rk[(ty * 8 + t) * 16 + tx] = mink[t];
    }
    __syncthreads();
    if (tid < TM) {
        float bv = rv[tid * 16];
        int   bk = rk[tid * 16];
#pragma unroll
        for (int j = 1; j < 16; j++) {
            float v = rv[tid * 16 + j];
            int   k = rk[tid * 16 + j];
            if (v < bv || (v == bv && k < bk)) { bv = v; bk = k; }
        }
        sidx[tid] = bk;
        discrete[(size_t)(m0 + tid) * KCODES + bk] = 1.0f;
        atomicAdd(&g_cnt[bk], 1.0f);
    }
    __syncthreads();

    // quantized[m0+t][:] = codebook[idx]; EMA weight numerator scatter-add.
    for (int it = 0; it < (TM * DIM) / 256; it++) {   // 32 iters
        int i = tid + it * 256;
        int t = i >> 6, d = i & 63;
        int k = sidx[t];
        quantized[(size_t)(m0 + t) * DIM + d] = cb[(size_t)k * DIM + d];
        atomicAdd(&g_wsum[k * DIM + d], xs[d * PADM + t]);
    }
}

// ---------------- kernel 2: EMA finalize ----------------
__global__ void vq_finalize(const float* __restrict__ ema_count,
                            const float* __restrict__ ema_weight,
                            float* __restrict__ ocount,
                            float* __restrict__ oweight,
                            float* __restrict__ ocb) {
    int i = blockIdx.x * blockDim.x + threadIdx.x;
    if (i >= KCODES * DIM) return;
    int k = i >> 6, d = i & 63;
    float cnt  = ema_count[k] * DECAYF + g_cnt[k] * OMDF;
    float norm = (cnt + EPSV) / (BATCHF + (float)KCODES * EPSV) * BATCHF;
    if (d == 0) ocount[k] = norm;
    float w = ema_weight[i] * DECAYF + g_wsum[i] * OMDF;
    oweight[i] = w;
    ocb[i]     = w / norm;
}

// ---------------- launch ----------------
extern "C" void kernel_launch(void* const* d_in, const int* in_sizes, int n_in,
                              void* d_out, int out_size) {
    const float* x  = (const float*)d_in[0];
    const float* cb = (const float*)d_in[1];
    const float* ec = (const float*)d_in[2];
    const float* ew = (const float*)d_in[3];

    float* out       = (float*)d_out;
    float* discrete  = out;                                  // N*K
    float* quantized = discrete + (size_t)NTOK * KCODES;     // N*D
    float* ocount    = quantized + (size_t)NTOK * DIM;       // K
    float* oweight   = ocount + KCODES;                      // K*D
    float* ocb       = oweight + (size_t)KCODES * DIM;       // K*D

    vq_prep<<<(KCODES * DIM + 255) / 256, 256>>>(cb);

    const int smem_bytes = (DIM * PADM + DIM * PADN) * (int)sizeof(float);  // 67584
    cudaFuncSetAttribute((const void*)vq_argmin,
                         cudaFuncAttributeMaxDynamicSharedMemorySize, smem_bytes);
    vq_argmin<<<NTOK / TM, 256, smem_bytes>>>(x, cb, discrete, quantized);

    vq_finalize<<<(KCODES * DIM + 255) / 256, 256>>>(ec, ew, ocount, oweight, ocb);
}

// round 5
// speedup vs baseline: 2.3822x; 2.2987x over previous
#include <cuda_runtime.h>
#include <cuda_bf16.h>
#include <cstdint>

// VectorQuantizerEMA: N=16384 tokens, K=8192 codes, D=64.
// Outputs (fp32, concat): discrete[N*K], quantized[N*D], new_count[K],
// new_weight[K*D], new_codebook[K*D].

#define NTOK   16384
#define KCODES 8192
#define DIM    64
#define TM     128
#define TN     128
#define NCH    (KCODES / TN)   // 64
#define DECAYF 0.99f
#define OMDF   0.01f
#define EPSV   1e-5f
#define BATCHF 32.0f

// smem layout (bytes): two B chunk buffers + x staging (reused for reduction)
#define OFF_BUF0 0
#define OFF_BUF1 32768
#define OFF_X    65536          // xh 16KB @ +0, xl 16KB @ +16384
#define SMEM_BYTES 98304

// ---------------- device scratch ----------------
__device__ __align__(128) __nv_bfloat16 g_cbh[KCODES * DIM];
__device__ __align__(128) __nv_bfloat16 g_cbl[KCODES * DIM];
__device__ float g_cnorm[KCODES];
__device__ float g_cnt[KCODES];
__device__ float g_wsum[KCODES * DIM];

// ---------------- PTX helpers (all base-target legal: sm_80/90 era) ----------------
__device__ __forceinline__ uint32_t smem_u32(const void* p) {
    uint32_t a;
    asm("{ .reg .u64 t; cvta.to.shared.u64 t, %1; cvt.u32.u64 %0, t; }" : "=r"(a) : "l"(p));
    return a;
}
__device__ __forceinline__ void ldsm4(uint32_t* r, uint32_t addr) {
    asm volatile("ldmatrix.sync.aligned.m8n8.x4.shared.b16 {%0,%1,%2,%3}, [%4];"
                 : "=r"(r[0]), "=r"(r[1]), "=r"(r[2]), "=r"(r[3]) : "r"(addr));
}
__device__ __forceinline__ void mma16816(float* c, const uint32_t* a, uint32_t b0, uint32_t b1) {
    asm volatile("mma.sync.aligned.m16n8k16.row.col.f32.bf16.bf16.f32 "
                 "{%0,%1,%2,%3}, {%4,%5,%6,%7}, {%8,%9}, {%0,%1,%2,%3};"
                 : "+f"(c[0]), "+f"(c[1]), "+f"(c[2]), "+f"(c[3])
                 : "r"(a[0]), "r"(a[1]), "r"(a[2]), "r"(a[3]), "r"(b0), "r"(b1));
}
__device__ __forceinline__ void cp16(uint32_t dst, const void* src) {
    asm volatile("cp.async.cg.shared.global [%0], [%1], 16;" :: "r"(dst), "l"(src));
}
#define CP_COMMIT() asm volatile("cp.async.commit_group;" ::: "memory")
#define CP_WAIT1()  asm volatile("cp.async.wait_group 1;" ::: "memory")

__device__ __forceinline__ void ins2(float& V1, int& K1, float& V2, int& K2, float v, int k) {
    if (v < V1) { V2 = V1; K2 = K1; V1 = v; K1 = k; }
    else if (v < V2) { V2 = v; K2 = k; }
}
__device__ __forceinline__ float dotrow(const float* xr, const float* cr) {
    float s = 0.f;
#pragma unroll
    for (int j = 0; j < 16; j++) {
        float4 a = ((const float4*)xr)[j];
        float4 b = ((const float4*)cr)[j];
        s += a.x * b.x + a.y * b.y + a.z * b.z + a.w * b.w;
    }
    return s;
}

// Stage one 128-code chunk (bf16 hi+lo, 32KB) into a smem buffer, SW128-swizzled.
__device__ __forceinline__ void stage_chunk(uint32_t sb, int chunk, uint32_t bufoff, int tid) {
    const char* srcH = (const char*)g_cbh + (size_t)chunk * 16384;
    const char* srcL = (const char*)g_cbl + (size_t)chunk * 16384;
#pragma unroll
    for (int i = 0; i < 8; i++) {
        int g = tid + i * 256;
        int ty = g >> 10, gg = g & 1023;
        int row = gg >> 3, c = gg & 7;
        const char* src = (ty ? srcL : srcH) + gg * 16;
        uint32_t dst = sb + bufoff + ty * 16384 + row * 128 + ((c * 16) ^ ((row & 7) << 4));
        cp16(dst, src);
    }
}

// ---------------- kernel 0: norms, bf16 split, zero accumulators ----------------
__global__ void vq_prep(const float* __restrict__ cb) {
    int g = blockIdx.x * blockDim.x + threadIdx.x;   // KCODES*DIM threads
    float v = cb[g];
    __nv_bfloat16 h = __float2bfloat16(v);
    g_cbh[g] = h;
    g_cbl[g] = __float2bfloat16(v - __bfloat162float(h));
    g_wsum[g] = 0.0f;
    if (g < KCODES) {
        g_cnt[g] = 0.0f;
        const float4* r = (const float4*)(cb + (size_t)g * DIM);
        float s = 0.0f;
#pragma unroll
        for (int j = 0; j < 16; j++) {
            float4 q = r[j];
            s += q.x * q.x + q.y * q.y + q.z * q.z + q.w * q.w;
        }
        g_cnorm[g] = s;
    }
}

// ---------------- kernel 1: mma.sync distances + fused argmin + outputs ----------------
extern "C" __global__ void __launch_bounds__(256)
vq_main(const float* __restrict__ x, const float* __restrict__ cb,
        float* __restrict__ discrete, float* __restrict__ quantized) {
    extern __shared__ char smem[];
    const uint32_t sb = smem_u32(smem);
    const int tid = threadIdx.x, lane = tid & 31, wid = tid >> 5;
    const int mw = wid >> 1, nc = wid & 1;           // 4 m-rows x 2 n-cols of warps
    const int mbase = mw * 32, nbase = nc * 64;
    const int m0 = blockIdx.x * TM;
    const int qid = lane & 3;

    // ---- stage x tile: fp32 -> bf16 hi/lo, SW128 rows of 128B ----
    for (int i = tid; i < TM * DIM; i += 256) {
        int t = i >> 6, d = i & 63;
        float v = x[(size_t)(m0 + t) * DIM + d];
        __nv_bfloat16 h = __float2bfloat16(v);
        __nv_bfloat16 l = __float2bfloat16(v - __bfloat162float(h));
        uint32_t swz = (uint32_t)((d * 2) ^ ((t & 7) << 4));
        *(__nv_bfloat16*)(smem + OFF_X + t * 128 + swz) = h;
        *(__nv_bfloat16*)(smem + OFF_X + 16384 + t * 128 + swz) = l;
    }
    // ---- prefetch first two B chunks ----
    stage_chunk(sb, 0, OFF_BUF0, tid); CP_COMMIT();
    stage_chunk(sb, 1, OFF_BUF1, tid); CP_COMMIT();
    __syncthreads();

    // ---- load A fragments once (held in regs for the whole kernel) ----
    uint32_t afr[2][4][2][4];   // [m-tile][k-step][hi/lo][reg]
#pragma unroll
    for (int mt = 0; mt < 2; mt++)
#pragma unroll
        for (int ks = 0; ks < 4; ks++)
#pragma unroll
            for (int ty = 0; ty < 2; ty++) {
                int rowA = mbase + mt * 16 + (lane & 15);
                int byteA = ks * 32 + ((lane & 16) ? 16 : 0);
                uint32_t a = sb + OFF_X + ty * 16384 + rowA * 128 + (byteA ^ ((rowA & 7) << 4));
                ldsm4(afr[mt][ks][ty], a);
            }

    // B ldsm per-lane invariants
    const uint32_t bRow = (uint32_t)(nbase + (lane & 7) + ((lane & 16) ? 8 : 0));
    const uint32_t bSwz = (bRow & 7) << 4;
    const uint32_t bByte = (lane & 8) ? 16u : 0u;

    // per-token-row top-2 trackers (4 rows per thread)
    float tv1[4], tv2[4];
    int   tk1[4], tk2[4];
#pragma unroll
    for (int i = 0; i < 4; i++) { tv1[i] = 3.4e38f; tv2[i] = 3.4e38f; tk1[i] = 0; tk2[i] = 0; }

    const float4 z4 = make_float4(0.f, 0.f, 0.f, 0.f);
    float acc[2][8][4];

    for (int ch = 0; ch < NCH; ch++) {
        // prefetch this chunk's codebook norms (L1/L2 resident)
        float2 nv[8];
        const float2* cnp = (const float2*)(g_cnorm + ch * TN + nbase);
#pragma unroll
        for (int nt = 0; nt < 8; nt++) nv[nt] = __ldg(&cnp[nt * 4 + qid]);

        CP_WAIT1();
        __syncthreads();

#pragma unroll
        for (int mt = 0; mt < 2; mt++)
#pragma unroll
            for (int nt = 0; nt < 8; nt++)
#pragma unroll
                for (int r = 0; r < 4; r++) acc[mt][nt][r] = 0.f;

        const uint32_t bufb = (ch & 1) ? OFF_BUF1 : OFF_BUF0;
#pragma unroll
        for (int ks = 0; ks < 4; ks++) {
            uint32_t bh[4][4], bl[4][4];
#pragma unroll
            for (int j = 0; j < 4; j++)
                ldsm4(bh[j], sb + bufb + (bRow + j * 16) * 128 + ((bByte + ks * 32) ^ bSwz));
#pragma unroll
            for (int j = 0; j < 4; j++)
                ldsm4(bl[j], sb + bufb + 16384 + (bRow + j * 16) * 128 + ((bByte + ks * 32) ^ bSwz));
            // xh*ch + xl*ch + xh*cl
#pragma unroll
            for (int mt = 0; mt < 2; mt++)
#pragma unroll
                for (int j = 0; j < 4; j++)
#pragma unroll
                    for (int h = 0; h < 2; h++) {
                        float* c = acc[mt][j * 2 + h];
                        mma16816(c, afr[mt][ks][0], bh[j][h * 2], bh[j][h * 2 + 1]);
                        mma16816(c, afr[mt][ks][1], bh[j][h * 2], bh[j][h * 2 + 1]);
                        mma16816(c, afr[mt][ks][0], bl[j][h * 2], bl[j][h * 2 + 1]);
                    }
        }

        // interleaved streaming zero-fill: 64KB slice of this block's discrete slab
        {
            float4* zb = (float4*)(discrete + (size_t)m0 * KCODES) + (size_t)ch * 4096;
#pragma unroll
            for (int i = 0; i < 16; i++) __stcs(&zb[tid + i * 256], z4);
        }

        // epilogue: dist = ||c||^2 - 2*dot ; top-2 track per token row
        const int kc = ch * TN + nbase + qid * 2;
#pragma unroll
        for (int mt = 0; mt < 2; mt++)
#pragma unroll
            for (int nt = 0; nt < 8; nt++) {
                const float* c = acc[mt][nt];
                const int kk = kc + nt * 8;
                float d0 = fmaf(c[0], -2.0f, nv[nt].x);
                float d1 = fmaf(c[1], -2.0f, nv[nt].y);
                float d2 = fmaf(c[2], -2.0f, nv[nt].x);
                float d3 = fmaf(c[3], -2.0f, nv[nt].y);
                ins2(tv1[mt * 2], tk1[mt * 2], tv2[mt * 2], tk2[mt * 2], d0, kk);
                ins2(tv1[mt * 2], tk1[mt * 2], tv2[mt * 2], tk2[mt * 2], d1, kk + 1);
                ins2(tv1[mt * 2 + 1], tk1[mt * 2 + 1], tv2[mt * 2 + 1], tk2[mt * 2 + 1], d2, kk);
                ins2(tv1[mt * 2 + 1], tk1[mt * 2 + 1], tv2[mt * 2 + 1], tk2[mt * 2 + 1], d3, kk + 1);
            }

        __syncthreads();     // everyone done reading buf (ch&1) before refill
        if (ch + 2 < NCH) stage_chunk(sb, ch + 2, bufb, tid);
        CP_COMMIT();
    }

    // ---- cross-thread reduction (reuse x staging smem) ----
    float* sv = (float*)(smem + OFF_X);            // 2048 floats
    int*   sk = (int*)(smem + OFF_X + 8192);       // 2048 ints
    int*   sidx = (int*)(smem + OFF_X + 16384);    // 128 ints
#pragma unroll
    for (int tr = 0; tr < 4; tr++) {
        int s = ((wid * 32 + lane) * 4 + tr) * 2;
        sv[s] = tv1[tr]; sk[s] = tk1[tr];
        sv[s + 1] = tv2[tr]; sk[s + 1] = tk2[tr];
    }
    __syncthreads();

    if (tid < TM) {
        const int t = tid;
        const int tmw = t >> 5, rloc = t & 31;
        const int mt = rloc >> 4, sub = (rloc >> 3) & 1, l4 = rloc & 7;
        const int tr = mt * 2 + sub;
        float V1 = 3.4e38f, V2 = 3.4e38f;
        int K1 = 0, K2 = 0;
#pragma unroll
        for (int ncc = 0; ncc < 2; ncc++)
#pragma unroll
            for (int c = 0; c < 4; c++) {
                int s = (((tmw * 2 + ncc) * 32 + l4 * 4 + c) * 4 + tr) * 2;
                float v1 = sv[s]; int k1 = sk[s];
                float v2 = sv[s + 1]; int k2 = sk[s + 1];
                if (v1 < V1 || (v1 == V1 && k1 < K1)) { V2 = V1; K2 = K1; V1 = v1; K1 = k1; }
                else if (v1 < V2 || (v1 == V2 && k1 < K2)) { V2 = v1; K2 = k1; }
                if (v2 < V2 || (v2 == V2 && k2 < K2)) {
                    if (v2 < V1 || (v2 == V1 && k2 < K1)) { V2 = V1; K2 = K1; V1 = v2; K1 = k2; }
                    else { V2 = v2; K2 = k2; }
                }
            }
        // exact fp32 rescue of top-2 -> argmin matches reference bit-exactly
        const float* xr = x + (size_t)(m0 + t) * DIM;
        float d1 = g_cnorm[K1] - 2.0f * dotrow(xr, cb + (size_t)K1 * DIM);
        float d2 = g_cnorm[K2] - 2.0f * dotrow(xr, cb + (size_t)K2 * DIM);
        int kw = (d2 < d1 || (d2 == d1 && K2 < K1)) ? K2 : K1;
        sidx[t] = kw;
        discrete[(size_t)(m0 + t) * KCODES + kw] = 1.0f;
        atomicAdd(&g_cnt[kw], 1.0f);
    }
    __syncthreads();

    // quantized gather + EMA weight numerator scatter
    for (int i = tid; i < TM * DIM; i += 256) {
        int t = i >> 6, d = i & 63;
        int k = sidx[t];
        quantized[(size_t)(m0 + t) * DIM + d] = cb[(size_t)k * DIM + d];
        atomicAdd(&g_wsum[k * DIM + d], x[(size_t)(m0 + t) * DIM + d]);
    }
}

// ---------------- kernel 2: EMA finalize ----------------
__global__ void vq_finalize(const float* __restrict__ ema_count,
                            const float* __restrict__ ema_weight,
                            float* __restrict__ ocount,
                            float* __restrict__ oweight,
                            float* __restrict__ ocb) {
    int i = blockIdx.x * blockDim.x + threadIdx.x;
    if (i >= KCODES * DIM) return;
    int k = i >> 6, d = i & 63;
    float cnt  = ema_count[k] * DECAYF + g_cnt[k] * OMDF;
    float norm = (cnt + EPSV) / (BATCHF + (float)KCODES * EPSV) * BATCHF;
    if (d == 0) ocount[k] = norm;
    float w = ema_weight[i] * DECAYF + g_wsum[i] * OMDF;
    oweight[i] = w;
    ocb[i]     = w / norm;
}

// ---------------- launch ----------------
extern "C" void kernel_launch(void* const* d_in, const int* in_sizes, int n_in,
                              void* d_out, int out_size) {
    const float* x  = (const float*)d_in[0];
    const float* cb = (const float*)d_in[1];
    const float* ec = (const float*)d_in[2];
    const float* ew = (const float*)d_in[3];

    float* out       = (float*)d_out;
    float* discrete  = out;                               // N*K
    float* quantized = discrete + (size_t)NTOK * KCODES;  // N*D
    float* ocount    = quantized + (size_t)NTOK * DIM;    // K
    float* oweight   = ocount + KCODES;                   // K*D
    float* ocb       = oweight + (size_t)KCODES * DIM;    // K*D

    vq_prep<<<(KCODES * DIM) / 256, 256>>>(cb);

    cudaFuncSetAttribute((const void*)vq_main,
                         cudaFuncAttributeMaxDynamicSharedMemorySize, SMEM_BYTES);
    vq_main<<<NTOK / TM, 256, SMEM_BYTES>>>(x, cb, discrete, quantized);

    vq_finalize<<<(KCODES * DIM + 255) / 256, 256>>>(ec, ew, ocount, oweight, ocb);
}

// round 8
// speedup vs baseline: 3.4110x; 1.4319x over previous
#include <cuda_runtime.h>
#include <cuda_bf16.h>
#include <cstdint>

// VectorQuantizerEMA: N=16384 tokens, K=8192 codes, D=64.
// Outputs (fp32, concat): discrete[N*K], quantized[N*D], new_count[K],
// new_weight[K*D], new_codebook[K*D].

#define NTOK   16384
#define KCODES 8192
#define DIM    64
#define TM     128
#define TN     128
#define NCH    (KCODES / TN)   // 64
#define DECAYF 0.99f
#define OMDF   0.01f
#define EPSV   1e-5f
#define BATCHF 32.0f

// smem layout (bytes): 3-buffer B ring (hi only) + x staging (reused for reduction)
#define OFF_BUF(i) ((i) * 16384)
#define OFF_X      49152          // xh 16KB; reused as reduction scratch at the end
#define SMEM_BYTES 66560

// ---------------- device scratch ----------------
__device__ __align__(128) __nv_bfloat16 g_cbh[KCODES * DIM];
__device__ float g_cnorm[KCODES];
__device__ float g_cnt[KCODES];
__device__ float g_wsum[KCODES * DIM];

// ---------------- PTX helpers (base-target legal) ----------------
__device__ __forceinline__ uint32_t smem_u32(const void* p) {
    uint32_t a;
    asm("{ .reg .u64 t; cvta.to.shared.u64 t, %1; cvt.u32.u64 %0, t; }" : "=r"(a) : "l"(p));
    return a;
}
__device__ __forceinline__ void ldsm4(uint32_t* r, uint32_t addr) {
    asm volatile("ldmatrix.sync.aligned.m8n8.x4.shared.b16 {%0,%1,%2,%3}, [%4];"
                 : "=r"(r[0]), "=r"(r[1]), "=r"(r[2]), "=r"(r[3]) : "r"(addr));
}
__device__ __forceinline__ void mma16816(float* c, const uint32_t* a, uint32_t b0, uint32_t b1) {
    asm volatile("mma.sync.aligned.m16n8k16.row.col.f32.bf16.bf16.f32 "
                 "{%0,%1,%2,%3}, {%4,%5,%6,%7}, {%8,%9}, {%0,%1,%2,%3};"
                 : "+f"(c[0]), "+f"(c[1]), "+f"(c[2]), "+f"(c[3])
                 : "r"(a[0]), "r"(a[1]), "r"(a[2]), "r"(a[3]), "r"(b0), "r"(b1));
}
__device__ __forceinline__ void cp16(uint32_t dst, const void* src) {
    asm volatile("cp.async.cg.shared.global [%0], [%1], 16;" :: "r"(dst), "l"(src));
}
#define CP_COMMIT() asm volatile("cp.async.commit_group;" ::: "memory")
#define CP_WAIT1()  asm volatile("cp.async.wait_group 1;" ::: "memory")

__device__ __forceinline__ void ins2(float& V1, int& K1, float& V2, int& K2, float v, int k) {
    if (v < V1) { V2 = V1; K2 = K1; V1 = v; K1 = k; }
    else if (v < V2) { V2 = v; K2 = k; }
}
__device__ __forceinline__ void ins4(float* V, int* KI, float v, int k) {
    if (v < V[3]) {
        if (v < V[1]) {
            V[3] = V[2]; KI[3] = KI[2]; V[2] = V[1]; KI[2] = KI[1];
            if (v < V[0]) { V[1] = V[0]; KI[1] = KI[0]; V[0] = v; KI[0] = k; }
            else { V[1] = v; KI[1] = k; }
        } else {
            if (v < V[2]) { V[3] = V[2]; KI[3] = KI[2]; V[2] = v; KI[2] = k; }
            else { V[3] = v; KI[3] = k; }
        }
    }
}
__device__ __forceinline__ float dotrow(const float* xr, const float* cr) {
    float s = 0.f;
#pragma unroll
    for (int j = 0; j < 16; j++) {
        float4 a = ((const float4*)xr)[j];
        float4 b = ((const float4*)cr)[j];
        s += a.x * b.x + a.y * b.y + a.z * b.z + a.w * b.w;
    }
    return s;
}

// Stage one 128-code chunk (bf16 hi, 16KB) into a smem ring buffer, SW128-swizzled.
__device__ __forceinline__ void stage_chunk(uint32_t sb, int chunk, uint32_t bufoff, int tid) {
    const char* src = (const char*)g_cbh + (size_t)chunk * 16384;
#pragma unroll
    for (int i = 0; i < 4; i++) {
        int gg = tid + i * 256;          // 0..1023 uint4s
        int row = gg >> 3, c = gg & 7;
        uint32_t dst = sb + bufoff + row * 128 + ((c * 16) ^ ((row & 7) << 4));
        cp16(dst, src + gg * 16);
    }
}

// ---------------- kernel 0: norms, bf16 cast, zero accumulators ----------------
__global__ void vq_prep(const float* __restrict__ cb) {
    int g = blockIdx.x * blockDim.x + threadIdx.x;   // KCODES*DIM threads
    float v = cb[g];
    g_cbh[g] = __float2bfloat16(v);
    g_wsum[g] = 0.0f;
    if (g < KCODES) {
        g_cnt[g] = 0.0f;
        const float4* r = (const float4*)(cb + (size_t)g * DIM);
        float s = 0.0f;
#pragma unroll
        for (int j = 0; j < 16; j++) {
            float4 q = r[j];
            s += q.x * q.x + q.y * q.y + q.z * q.z + q.w * q.w;
        }
        g_cnorm[g] = s;
    }
}

// ---------------- kernel 1: bf16 screening GEMM + top-4 exact rescue + outputs ----------------
extern "C" __global__ void __launch_bounds__(256)
vq_main(const float* __restrict__ x, const float* __restrict__ cb,
        float* __restrict__ discrete, float* __restrict__ quantized) {
    extern __shared__ char smem[];
    const uint32_t sb = smem_u32(smem);
    const int tid = threadIdx.x, lane = tid & 31, wid = tid >> 5;
    const int mw = wid >> 1, nc = wid & 1;           // 4 m-rows x 2 n-cols of warps
    const int mbase = mw * 32, nbase = nc * 64;
    const int m0 = blockIdx.x * TM;
    const int qid = lane & 3;

    // ---- stage x tile: fp32 -> bf16 hi, SW128 rows of 128B ----
    for (int i = tid; i < TM * DIM; i += 256) {
        int t = i >> 6, d = i & 63;
        float v = x[(size_t)(m0 + t) * DIM + d];
        uint32_t swz = (uint32_t)((d * 2) ^ ((t & 7) << 4));
        *(__nv_bfloat16*)(smem + OFF_X + t * 128 + swz) = __float2bfloat16(v);
    }
    // ---- prefetch first two B chunks ----
    stage_chunk(sb, 0, OFF_BUF(0), tid); CP_COMMIT();
    stage_chunk(sb, 1, OFF_BUF(1), tid); CP_COMMIT();
    __syncthreads();

    // ---- A fragments loaded once, held in regs ----
    uint32_t afr[2][4][4];   // [m-tile][k-step][reg]
#pragma unroll
    for (int mt = 0; mt < 2; mt++)
#pragma unroll
        for (int ks = 0; ks < 4; ks++) {
            int rowA = mbase + mt * 16 + (lane & 15);
            int byteA = ks * 32 + ((lane & 16) ? 16 : 0);
            ldsm4(afr[mt][ks], sb + OFF_X + rowA * 128 + (byteA ^ ((rowA & 7) << 4)));
        }

    // B ldsm per-lane invariants
    const uint32_t bRow = (uint32_t)(nbase + (lane & 7) + ((lane & 16) ? 8 : 0));
    const uint32_t bSwz = (bRow & 7) << 4;
    const uint32_t bByte = (lane & 8) ? 16u : 0u;

    // per-token-row top-2 trackers (4 rows per thread)
    float tv1[4], tv2[4];
    int   tk1[4], tk2[4];
#pragma unroll
    for (int i = 0; i < 4; i++) { tv1[i] = 3.4e38f; tv2[i] = 3.4e38f; tk1[i] = 0; tk2[i] = 0; }

    const float4 z4 = make_float4(0.f, 0.f, 0.f, 0.f);
    float acc[2][8][4];

    for (int ch = 0; ch < NCH; ch++) {
        CP_WAIT1();
        __syncthreads();   // chunk ch visible; ring buffer (ch+2)%3 free since ch-1

        // stage-ahead: fill (ch+2)%3 while everyone reads ch%3 (no trailing sync needed)
        if (ch + 2 < NCH) stage_chunk(sb, ch + 2, OFF_BUF((ch + 2) % 3), tid);
        CP_COMMIT();       // unconditional: keeps group counter aligned with chunk index

        // codebook norms for this warp's 64-column slice
        float2 nv[8];
        const float2* cnp = (const float2*)(g_cnorm + ch * TN + nbase);
#pragma unroll
        for (int nt = 0; nt < 8; nt++) nv[nt] = __ldg(&cnp[nt * 4 + qid]);

#pragma unroll
        for (int mt = 0; mt < 2; mt++)
#pragma unroll
            for (int nt = 0; nt < 8; nt++)
#pragma unroll
                for (int r = 0; r < 4; r++) acc[mt][nt][r] = 0.f;

        const uint32_t bufb = OFF_BUF(ch % 3);
#pragma unroll
        for (int ks = 0; ks < 4; ks++) {
            uint32_t bh[4][4];
#pragma unroll
            for (int j = 0; j < 4; j++)
                ldsm4(bh[j], sb + bufb + (bRow + j * 16) * 128 + ((bByte + ks * 32) ^ bSwz));
#pragma unroll
            for (int mt = 0; mt < 2; mt++)
#pragma unroll
                for (int j = 0; j < 4; j++)
#pragma unroll
                    for (int h = 0; h < 2; h++)
                        mma16816(acc[mt][j * 2 + h], afr[mt][ks], bh[j][h * 2], bh[j][h * 2 + 1]);
        }

        // interleaved streaming zero-fill: 64KB slice of this block's discrete slab
        {
            float4* zb = (float4*)(discrete + (size_t)m0 * KCODES) + (size_t)ch * 4096;
#pragma unroll
            for (int i = 0; i < 16; i++) __stcs(&zb[tid + i * 256], z4);
        }

        // gated epilogue: approx dist = ||c||^2 - 2*dot_hi ; track top-2 per token row
        const int kc = ch * TN + nbase + qid * 2;
#pragma unroll
        for (int mt = 0; mt < 2; mt++)
#pragma unroll
            for (int nt = 0; nt < 8; nt++) {
                const float* c = acc[mt][nt];
                const int kk = kc + nt * 8;
                float d0 = fmaf(c[0], -2.0f, nv[nt].x);
                float d1 = fmaf(c[1], -2.0f, nv[nt].y);
                float d2 = fmaf(c[2], -2.0f, nv[nt].x);
                float d3 = fmaf(c[3], -2.0f, nv[nt].y);
                const int r0 = mt * 2, r1 = mt * 2 + 1;
                if (fminf(d0, d1) < tv2[r0]) {
                    ins2(tv1[r0], tk1[r0], tv2[r0], tk2[r0], d0, kk);
                    ins2(tv1[r0], tk1[r0], tv2[r0], tk2[r0], d1, kk + 1);
                }
                if (fminf(d2, d3) < tv2[r1]) {
                    ins2(tv1[r1], tk1[r1], tv2[r1], tk2[r1], d2, kk);
                    ins2(tv1[r1], tk1[r1], tv2[r1], tk2[r1], d3, kk + 1);
                }
            }
    }

    // ---- cross-thread reduction (reuse x staging smem) ----
    __syncthreads();
    float* sv = (float*)(smem + OFF_X);            // 2048 floats
    int*   sk = (int*)(smem + OFF_X + 8192);       // 2048 ints
    int*   sidx = (int*)(smem + OFF_X + 16384);    // 128 ints
#pragma unroll
    for (int tr = 0; tr < 4; tr++) {
        int s = ((wid * 32 + lane) * 4 + tr) * 2;
        sv[s] = tv1[tr]; sk[s] = tk1[tr];
        sv[s + 1] = tv2[tr]; sk[s + 1] = tk2[tr];
    }
    __syncthreads();

    if (tid < TM) {
        const int t = tid;
        const int tmw = t >> 5, rloc = t & 31;
        const int mt = rloc >> 4, sub = (rloc >> 3) & 1, l4 = rloc & 7;
        const int tr = mt * 2 + sub;
        float V[4] = {3.4e38f, 3.4e38f, 3.4e38f, 3.4e38f};
        int KI[4] = {0, 0, 0, 0};
#pragma unroll
        for (int ncc = 0; ncc < 2; ncc++)
#pragma unroll
            for (int c = 0; c < 4; c++) {
                int s = (((tmw * 2 + ncc) * 32 + l4 * 4 + c) * 4 + tr) * 2;
                ins4(V, KI, sv[s], sk[s]);
                ins4(V, KI, sv[s + 1], sk[s + 1]);
            }
        // exact fp32 rescue of approx top-4 -> argmin matches reference
        const float* xr = x + (size_t)(m0 + t) * DIM;
        float bd = 3.4e38f; int bk = 0x7fffffff;
#pragma unroll
        for (int i = 0; i < 4; i++) {
            int k = KI[i];
            float d = g_cnorm[k] - 2.0f * dotrow(xr, cb + (size_t)k * DIM);
            if (d < bd || (d == bd && k < bk)) { bd = d; bk = k; }
        }
        sidx[t] = bk;
        discrete[(size_t)(m0 + t) * KCODES + bk] = 1.0f;
        atomicAdd(&g_cnt[bk], 1.0f);
    }
    __syncthreads();

    // quantized gather + EMA weight numerator scatter
    for (int i = tid; i < TM * DIM; i += 256) {
        int t = i >> 6, d = i & 63;
        int k = sidx[t];
        quantized[(size_t)(m0 + t) * DIM + d] = cb[(size_t)k * DIM + d];
        atomicAdd(&g_wsum[k * DIM + d], x[(size_t)(m0 + t) * DIM + d]);
    }
}

// ---------------- kernel 2: EMA finalize ----------------
__global__ void vq_finalize(const float* __restrict__ ema_count,
                            const float* __restrict__ ema_weight,
                            float* __restrict__ ocount,
                            float* __restrict__ oweight,
                            float* __restrict__ ocb) {
    int i = blockIdx.x * blockDim.x + threadIdx.x;
    if (i >= KCODES * DIM) return;
    int k = i >> 6, d = i & 63;
    float cnt  = ema_count[k] * DECAYF + g_cnt[k] * OMDF;
    float norm = (cnt + EPSV) / (BATCHF + (float)KCODES * EPSV) * BATCHF;
    if (d == 0) ocount[k] = norm;
    float w = ema_weight[i] * DECAYF + g_wsum[i] * OMDF;
    oweight[i] = w;
    ocb[i]     = w / norm;
}

// ---------------- launch ----------------
extern "C" void kernel_launch(void* const* d_in, const int* in_sizes, int n_in,
                              void* d_out, int out_size) {
    const float* x  = (const float*)d_in[0];
    const float* cb = (const float*)d_in[1];
    const float* ec = (const float*)d_in[2];
    const float* ew = (const float*)d_in[3];

    float* out       = (float*)d_out;
    float* discrete  = out;                               // N*K
    float* quantized = discrete + (size_t)NTOK * KCODES;  // N*D
    float* ocount    = quantized + (size_t)NTOK * DIM;    // K
    float* oweight   = ocount + KCODES;                   // K*D
    float* ocb       = oweight + (size_t)KCODES * DIM;    // K*D

    vq_prep<<<(KCODES * DIM) / 256, 256>>>(cb);

    cudaFuncSetAttribute((const void*)vq_main,
                         cudaFuncAttributeMaxDynamicSharedMemorySize, SMEM_BYTES);
    vq_main<<<NTOK / TM, 256, SMEM_BYTES>>>(x, cb, discrete, quantized);

    vq_finalize<<<(KCODES * DIM + 255) / 256, 256>>>(ec, ew, ocount, oweight, ocb);
}